// round 2
// baseline (speedup 1.0000x reference)
#include <cuda_runtime.h>
#include <cuda_bf16.h>

// Problem dims
#define S_ 512
#define B_ 128
#define E_ 100
#define H_ 256
#define T_ 9
#define G_ 1024   // 4*H

// ---------------- scratch (device globals; no allocations) ----------------
__device__ float g_xg[2][S_ * B_ * G_];   // input projections + bias, [dir][s][b][4H]
__device__ float g_h [2][S_ * B_ * H_];   // hidden states, [dir][s][b][H]
__device__ float g_em[B_ * S_ * T_];      // emissions [b][s][t]
__device__ int   g_bp[B_ * S_ * T_];      // viterbi backpointers (valid for t>=1)
__device__ unsigned g_bar[2];             // per-direction step barriers

__device__ __forceinline__ float sigmoidf(float x) { return 1.f / (1.f + expf(-x)); }

__global__ void reset_kernel() {
    if (threadIdx.x < 2) g_bar[threadIdx.x] = 0u;
}

// ---------------- Kernel A: embed gather + input projection -------------
// xg[dir][s][b][g] = sum_k emb[data[b][s]][k] * W_ih[g][k] + bias[g]
// CTA tile: 32 tokens x 128 gates. grid = (2048 token tiles, 16 gate tiles)
// gate tiles 0..7 -> forward, 8..15 -> backward.
__global__ void xg_kernel(const int* __restrict__ data,
                          const float* __restrict__ emb,
                          const float* __restrict__ Wf,
                          const float* __restrict__ bf,
                          const float* __restrict__ Wb,
                          const float* __restrict__ bb) {
    extern __shared__ float sm[];
    float* Xsm = sm;          // [100][36]  (32 tokens + pad)
    float* Wsm = sm + 3600;   // [100][132] (128 gates + pad)

    int tt  = blockIdx.x;
    int gt  = blockIdx.y;
    int dir = gt >> 3;
    int g0  = (gt & 7) * 128;
    const float* W    = dir ? Wb : Wf;
    const float* bias = dir ? bb : bf;

    // stage X tile (embedding gather), transposed [k][token]
    for (int idx = threadIdx.x; idx < 32 * E_; idx += 256) {
        int j = idx / E_, k = idx - j * E_;
        int tok = tt * 32 + j;            // tok = s*128 + b
        int s = tok >> 7, b = tok & 127;
        int row = data[b * S_ + s];       // 0 => emb row is all zeros
        Xsm[k * 36 + j] = emb[row * E_ + k];
    }
    // stage W tile, transposed [k][gate]
    for (int idx = threadIdx.x; idx < 128 * E_; idx += 256) {
        int r = idx / E_, k = idx - r * E_;
        Wsm[k * 132 + r] = W[(g0 + r) * E_ + k];
    }
    __syncthreads();

    int gg = threadIdx.x & 31;   // 32 gate groups x 4 gates
    int tg = threadIdx.x >> 5;   // 8 token groups x 4 tokens
    float acc[4][4];
#pragma unroll
    for (int i = 0; i < 4; i++)
#pragma unroll
        for (int j = 0; j < 4; j++) acc[i][j] = 0.f;

    const float* wp = &Wsm[gg * 4];
    const float* xp = &Xsm[tg * 4];
    for (int k = 0; k < E_; k++) {
        float4 w = *(const float4*)(wp + k * 132);
        float4 x = *(const float4*)(xp + k * 36);
        acc[0][0] += w.x * x.x; acc[0][1] += w.x * x.y; acc[0][2] += w.x * x.z; acc[0][3] += w.x * x.w;
        acc[1][0] += w.y * x.x; acc[1][1] += w.y * x.y; acc[1][2] += w.y * x.z; acc[1][3] += w.y * x.w;
        acc[2][0] += w.z * x.x; acc[2][1] += w.z * x.y; acc[2][2] += w.z * x.z; acc[2][3] += w.z * x.w;
        acc[3][0] += w.w * x.x; acc[3][1] += w.w * x.y; acc[3][2] += w.w * x.z; acc[3][3] += w.w * x.w;
    }

    float b0v = bias[g0 + gg * 4 + 0];
    float b1v = bias[g0 + gg * 4 + 1];
    float b2v = bias[g0 + gg * 4 + 2];
    float b3v = bias[g0 + gg * 4 + 3];
#pragma unroll
    for (int ti = 0; ti < 4; ti++) {
        int tok = tt * 32 + tg * 4 + ti;
        float4 o = make_float4(acc[0][ti] + b0v, acc[1][ti] + b1v,
                               acc[2][ti] + b2v, acc[3][ti] + b3v);
        *(float4*)&g_xg[dir][tok * G_ + g0 + gg * 4] = o;
    }
}

// ---------------- Kernel B: persistent bidirectional LSTM ----------------
// 128 CTAs, 256 threads. CTAs [0,64): forward, [64,128): backward.
// Per direction, CTA covers (32-batch tile) x (16-unit tile = 64 gate rows).
// W slice resident in SMEM for all 512 steps; h staged transposed each step.
// Thread = (1 unit, 2 batches): computes all 4 gates -> c,h in-register.
__global__ void __launch_bounds__(256, 1)
lstm_kernel(const float* __restrict__ Whhf, const float* __restrict__ Whhb) {
    extern __shared__ float sm[];
    float* Wsm = sm;              // [256][68]: [k][unit*4+gate]
    float* Hsm = sm + 256 * 68;   // [256][34]: [k][b_local]

    int dir = blockIdx.x >> 6;
    int cid = blockIdx.x & 63;
    int b0  = (cid & 3) * 32;
    int u0  = (cid >> 2) * 16;
    const float* Whh = dir ? Whhb : Whhf;

    // stage W slice: rows {gate*256 + u0+unit} for unit<16, gate<4
    for (int idx = threadIdx.x; idx < 64 * 256; idx += 256) {
        int r = idx >> 8, k = idx & 255;
        int unit = r >> 2, gate = r & 3;
        Wsm[k * 68 + unit * 4 + gate] = Whh[(gate * 256 + u0 + unit) * 256 + k];
    }

    int un = threadIdx.x & 15;       // local unit
    int bg = threadIdx.x >> 4;       // batch group (2 batches)
    int u  = u0 + un;
    int bA = b0 + bg * 2, bB = bA + 1;
    float c0 = 0.f, c1 = 0.f;
    volatile unsigned* bar = &g_bar[dir];

    for (int ts = 0; ts < S_; ts++) {
        int t = dir ? (S_ - 1 - ts) : ts;

        // prefetch xg for this step (independent of the barrier-gated h data)
        const float* xg = &g_xg[dir][(t * B_) * G_];
        float xa0 = xg[bA * G_ + 0 * 256 + u];
        float xa1 = xg[bA * G_ + 1 * 256 + u];
        float xa2 = xg[bA * G_ + 2 * 256 + u];
        float xa3 = xg[bA * G_ + 3 * 256 + u];
        float xb0 = xg[bB * G_ + 0 * 256 + u];
        float xb1 = xg[bB * G_ + 1 * 256 + u];
        float xb2 = xg[bB * G_ + 2 * 256 + u];
        float xb3 = xg[bB * G_ + 3 * 256 + u];

        float a00 = 0.f, a10 = 0.f, a20 = 0.f, a30 = 0.f;  // gates for bA
        float a01 = 0.f, a11 = 0.f, a21 = 0.f, a31 = 0.f;  // gates for bB

        if (ts > 0) {
            int tp = dir ? (t + 1) : (t - 1);
            // stage h_prev (our 32 batches) transposed into SMEM
            const float* hp = &g_h[dir][(tp * B_) * H_];
            for (int idx = threadIdx.x; idx < 32 * 64; idx += 256) {
                int j = idx >> 6;   // local batch
                int q = idx & 63;   // unit quad
                float4 hv = *(const float4*)&hp[(b0 + j) * H_ + q * 4];
                Hsm[(q * 4 + 0) * 34 + j] = hv.x;
                Hsm[(q * 4 + 1) * 34 + j] = hv.y;
                Hsm[(q * 4 + 2) * 34 + j] = hv.z;
                Hsm[(q * 4 + 3) * 34 + j] = hv.w;
            }
            __syncthreads();

            const float* wp  = &Wsm[un * 4];
            const float* hp2 = &Hsm[bg * 2];
#pragma unroll 4
            for (int k = 0; k < H_; k++) {
                float4 w  = *(const float4*)(wp + k * 68);
                float2 h2 = *(const float2*)(hp2 + k * 34);
                a00 += w.x * h2.x; a10 += w.y * h2.x; a20 += w.z * h2.x; a30 += w.w * h2.x;
                a01 += w.x * h2.y; a11 += w.y * h2.y; a21 += w.z * h2.y; a31 += w.w * h2.y;
            }
        }

        a00 += xa0; a10 += xa1; a20 += xa2; a30 += xa3;
        a01 += xb0; a11 += xb1; a21 += xb2; a31 += xb3;

        float i0 = sigmoidf(a00), f0 = sigmoidf(a10), g0v = tanhf(a20), o0 = sigmoidf(a30);
        c0 = f0 * c0 + i0 * g0v;
        float h0v = o0 * tanhf(c0);
        float i1 = sigmoidf(a01), f1 = sigmoidf(a11), g1v = tanhf(a21), o1 = sigmoidf(a31);
        c1 = f1 * c1 + i1 * g1v;
        float h1v = o1 * tanhf(c1);

        float* hout = &g_h[dir][(t * B_) * H_];
        hout[bA * H_ + u] = h0v;
        hout[bB * H_ + u] = h1v;

        // chip-wide (per-direction) step barrier: monotonic counter
        __threadfence();
        __syncthreads();
        if (threadIdx.x == 0) {
            atomicAdd((unsigned*)&g_bar[dir], 1u);
            unsigned target = 64u * (unsigned)(ts + 1);
            while (*bar < target) { }
            __threadfence();
        }
        __syncthreads();
    }
}

// ---------------- Kernel C: MLP emissions ----------------
// em[b][s][t] = sum_h [hf;hb][s][b][h] * mlp_W[t][h] + mlp_b[t]
__global__ void mlp_kernel(const float* __restrict__ mlpW,
                           const float* __restrict__ mlpb) {
    __shared__ float Wsm[T_ * 2 * H_];  // 9*512 = 4608 floats
    for (int i = threadIdx.x; i < T_ * 2 * H_; i += 256) Wsm[i] = mlpW[i];
    __syncthreads();

    int w = threadIdx.x >> 5, lane = threadIdx.x & 31;
    int tok = blockIdx.x * 8 + w;       // tok = s*128 + b
    int s = tok >> 7, b = tok & 127;

    float acc[T_];
#pragma unroll
    for (int t = 0; t < T_; t++) acc[t] = 0.f;

    const float* hf = &g_h[0][(s * B_ + b) * H_];
    const float* hb = &g_h[1][(s * B_ + b) * H_];
    for (int h = lane; h < H_; h += 32) {
        float v1 = hf[h];
        float v2 = hb[h];
#pragma unroll
        for (int t = 0; t < T_; t++) {
            acc[t] += v1 * Wsm[t * 512 + h];
            acc[t] += v2 * Wsm[t * 512 + 256 + h];
        }
    }
#pragma unroll
    for (int t = 0; t < T_; t++)
        for (int off = 16; off; off >>= 1)
            acc[t] += __shfl_xor_sync(0xFFFFFFFFu, acc[t], off);
    if (lane < T_)
        g_em[(b * S_ + s) * T_ + lane] = acc[lane] + mlpb[lane];
}

// ---------------- Kernel D: CRF Viterbi (one warp per batch) -------------
__global__ void viterbi_kernel(const int* __restrict__ data,
                               const float* __restrict__ stt,
                               const float* __restrict__ trn,
                               const float* __restrict__ ett,
                               float* __restrict__ out) {
    int w = threadIdx.x >> 5, lane = threadIdx.x & 31;
    int b = blockIdx.x * 4 + w;
    int cc = lane < T_ ? lane : (T_ - 1);

    // sequence length = count of nonzero tokens (contiguous prefix)
    int cnt = 0;
    for (int s = lane; s < S_; s += 32) cnt += (data[b * S_ + s] != 0);
    for (int off = 16; off; off >>= 1) cnt += __shfl_xor_sync(0xFFFFFFFFu, cnt, off);
    int len = cnt;

    float tr[T_];
#pragma unroll
    for (int p = 0; p < T_; p++) tr[p] = trn[p * T_ + cc];

    float score = stt[cc] + g_em[(b * S_ + 0) * T_ + cc];

    for (int t = 1; t < S_; t++) {
        float e = g_em[(b * S_ + t) * T_ + cc];
        float best = -1e30f; int bp = 0;
#pragma unroll
        for (int p = 0; p < T_; p++) {
            float sp = __shfl_sync(0xFFFFFFFFu, score, p);
            float cand = sp + tr[p] + e;
            if (cand > best) { best = cand; bp = p; }   // first-max tie-break
        }
        if (lane < T_) g_bp[(b * S_ + t) * T_ + lane] = bp;
        if (t < len) score = best;
    }

    float fin = score + ett[cc];
    float bestf = -1e30f; int tag = 0;
#pragma unroll
    for (int p = 0; p < T_; p++) {
        float v = __shfl_sync(0xFFFFFFFFu, fin, p);
        if (v > bestf) { bestf = v; tag = p; }
    }
    if (lane == 0) out[B_ * S_ + b] = bestf;

    if (lane == 0) out[b * S_ + (S_ - 1)] = ((S_ - 1) < len) ? (float)tag : 0.f;
    for (int s2 = S_ - 2; s2 >= 0; s2--) {
        int bpv = g_bp[(b * S_ + s2 + 1) * T_ + cc];
        int prev = __shfl_sync(0xFFFFFFFFu, bpv, tag);
        if (s2 + 1 < len) tag = prev;
        if (lane == 0) out[b * S_ + s2] = (s2 < len) ? (float)tag : 0.f;
    }
}

// ---------------- launch ----------------
extern "C" void kernel_launch(void* const* d_in, const int* in_sizes, int n_in,
                              void* d_out, int out_size) {
    const int*   data = (const int*)d_in[0];
    // d_in[1] = mask (ignored; mask == (data != 0))
    const float* emb  = (const float*)d_in[2];
    const float* Wihf = (const float*)d_in[3];
    const float* Whhf = (const float*)d_in[4];
    const float* bf   = (const float*)d_in[5];
    const float* Wihb = (const float*)d_in[6];
    const float* Whhb = (const float*)d_in[7];
    const float* bb   = (const float*)d_in[8];
    const float* mlpW = (const float*)d_in[9];
    const float* mlpb = (const float*)d_in[10];
    const float* stt  = (const float*)d_in[11];
    const float* trn  = (const float*)d_in[12];
    const float* ett  = (const float*)d_in[13];
    float* out = (float*)d_out;

    cudaFuncSetAttribute(xg_kernel,  cudaFuncAttributeMaxDynamicSharedMemorySize, 67200);
    cudaFuncSetAttribute(lstm_kernel, cudaFuncAttributeMaxDynamicSharedMemorySize, 104448);

    reset_kernel<<<1, 32>>>();
    dim3 gA(2048, 16);
    xg_kernel<<<gA, 256, 67200>>>(data, emb, Wihf, bf, Wihb, bb);
    lstm_kernel<<<128, 256, 104448>>>(Whhf, Whhb);
    mlp_kernel<<<8192, 256>>>(mlpW, mlpb);
    viterbi_kernel<<<32, 128>>>(data, stt, trn, ett, out);
}